// round 13
// baseline (speedup 1.0000x reference)
#include <cuda_runtime.h>
#include <cuda_fp16.h>
#include <math.h>
#include <stdint.h>

#define B_   2
#define S_   1024
#define E_   2048
#define NH_  16
#define DH_  128
#define EPS_ 1e-6f
#define NEC  24
#define ECH  256          // 6144 / 24, 4 sub-tiles

#define FMA2(d, a, b)  asm("fma.rn.f32x2 %0, %1, %2, %0;" : "+l"(d) : "l"(a), "l"(b))
#define PACK2(d, x)    asm("mov.b64 %0, {%1, %1};" : "=l"(d) : "f"(x))

__device__ __forceinline__ void cpa16(uint32_t dst, const void* src) {
    asm volatile("cp.async.ca.shared.global [%0], [%1], 16;" :: "r"(dst), "l"(src));
}
__device__ __forceinline__ void cpa_commit() { asm volatile("cp.async.commit_group;"); }

// ---------------- warp-MMA helpers (sm_80-era PTX: safe under compute_103) ----------------
static __device__ __forceinline__ uint32_t pack_hf2(float x0, float x1) {
    uint32_t r; asm("cvt.rn.f16x2.f32 %0, %1, %2;" : "=r"(r) : "f"(x1), "f"(x0)); return r;
}
static __device__ __forceinline__ float lo_hf(uint32_t p) {
    return __half2float(__ushort_as_half((unsigned short)(p & 0xFFFFu)));
}
static __device__ __forceinline__ float hi_hf(uint32_t p) {
    return __half2float(__ushort_as_half((unsigned short)(p >> 16)));
}

#define LDSM4(r, a) \
    asm volatile("ldmatrix.sync.aligned.m8n8.x4.shared.b16 {%0,%1,%2,%3}, [%4];" \
        : "=r"((r)[0]), "=r"((r)[1]), "=r"((r)[2]), "=r"((r)[3]) : "r"(a))
#define LDSM4T(r, a) \
    asm volatile("ldmatrix.sync.aligned.m8n8.x4.trans.shared.b16 {%0,%1,%2,%3}, [%4];" \
        : "=r"((r)[0]), "=r"((r)[1]), "=r"((r)[2]), "=r"((r)[3]) : "r"(a))

static __device__ __forceinline__ void mma16816h(float* c, const uint32_t* a, const uint32_t* b) {
    asm volatile("mma.sync.aligned.m16n8k16.row.col.f32.f16.f16.f32 "
        "{%0,%1,%2,%3}, {%4,%5,%6,%7}, {%8,%9}, {%0,%1,%2,%3};"
        : "+f"(c[0]), "+f"(c[1]), "+f"(c[2]), "+f"(c[3])
        : "r"(a[0]), "r"(a[1]), "r"(a[2]), "r"(a[3]), "r"(b[0]), "r"(b[1]));
}

__device__ float g_part[2 * NEC * B_ * NH_ * S_];
__device__ float g_a [B_ * NH_ * S_];
__device__ float g_rm[B_ * NH_ * S_];
__device__ float g_nl[B_ * NH_ * S_];

// ============== Kernel 1: gates (R8 structure; reg cap raised to ~85) ==============
__global__ __launch_bounds__(256, 3) void gates_partial_k(
    const float* __restrict__ q, const float* __restrict__ k, const float* __restrict__ v,
    const float* __restrict__ Wi, const float* __restrict__ Wf)
{
    __shared__ float Xs[2][64 * 68];
    __shared__ float Ws[2][64 * 32];
    const int rt = blockIdx.x, ec = blockIdx.y;
    const int b = rt >> 4, s0 = (rt & 15) << 6, t = threadIdx.x;
    const int rgrp = t >> 3, hgrp = t & 7;

    auto pf = [&](int sub, int bufi) {
        const int e0 = ec * ECH + sub * 64;
        const float* xp = (e0 < E_) ? q : (e0 < 2 * E_) ? k : v;
        const int col0 = e0 & (E_ - 1);
        float* xd = Xs[bufi];
        float* wd = Ws[bufi];
        #pragma unroll
        for (int c = 0; c < 4; ++c) {
            int idx = t + c * 256, r = idx >> 4, q4 = (idx & 15) * 4;
            cpa16((uint32_t)__cvta_generic_to_shared(xd + r * 68 + q4),
                  xp + ((size_t)(b * S_ + s0 + r)) * E_ + col0 + q4);
        }
        #pragma unroll
        for (int c = 0; c < 2; ++c) {
            int idx = t + c * 256, ee = idx >> 3, cc = idx & 7, eg = e0 + ee;
            const float* src = (cc < 4) ? (Wi + eg * 16 + cc * 4)
                                        : (Wf + eg * 16 + (cc - 4) * 4);
            cpa16((uint32_t)__cvta_generic_to_shared(wd + ee * 32 + cc * 4), src);
        }
        cpa_commit();
    };

    unsigned long long acc2[2][2] = {};
    pf(0, 0);
    #pragma unroll 1
    for (int sub = 0; sub < 4; ++sub) {
        const int bufi = sub & 1;
        if (sub < 3) {
            pf(sub + 1, bufi ^ 1);
            asm volatile("cp.async.wait_group 1;");
        } else {
            asm volatile("cp.async.wait_group 0;");
        }
        __syncthreads();
        const float* xs = Xs[bufi];
        const float* ws = Ws[bufi];
        #pragma unroll 8
        for (int ee = 0; ee < 64; ++ee) {
            unsigned long long xp2[2];
            #pragma unroll
            for (int m = 0; m < 2; ++m) { float xv = xs[(rgrp * 2 + m) * 68 + ee]; PACK2(xp2[m], xv); }
            ulonglong2 wv = *(const ulonglong2*)(ws + ee * 32 + hgrp * 4);
            #pragma unroll
            for (int m = 0; m < 2; ++m) { FMA2(acc2[m][0], xp2[m], wv.x); FMA2(acc2[m][1], xp2[m], wv.y); }
        }
        __syncthreads();
    }
    #pragma unroll
    for (int m = 0; m < 2; ++m) {
        int s = s0 + rgrp * 2 + m;
        #pragma unroll
        for (int p = 0; p < 2; ++p) {
            float2 u = *(float2*)&acc2[m][p];
            #pragma unroll
            for (int hh = 0; hh < 2; ++hh) {
                int hcol = hgrp * 4 + p * 2 + hh;
                g_part[(((hcol >> 4) * NEC + ec) * (B_ * NH_) + b * NH_ + (hcol & 15)) * S_ + s] = hh ? u.y : u.x;
            }
        }
    }
}

// ============== Kernel 2: scans ==============
__global__ __launch_bounds__(1024, 1) void scan_k(const float* __restrict__ bi, const float* __restrict__ bf)
{
    __shared__ float buf[1024];
    const int bh = blockIdx.x, t = threadIdx.x, h = bh & 15;
    float ig = bi[h], fg = bf[h];
    #pragma unroll
    for (int ec = 0; ec < NEC; ++ec) {
        ig += g_part[((0 * NEC + ec) * (B_ * NH_) + bh) * S_ + t];
        fg += g_part[((1 * NEC + ec) * (B_ * NH_) + bh) * S_ + t];
    }
    float lf = fminf(fg, 0.f) - log1pf(expf(-fabsf(fg)));
    float x = lf;
    buf[t] = x; __syncthreads();
    for (int off = 1; off < 1024; off <<= 1) {
        float y = (t >= off) ? buf[t - off] : 0.f; __syncthreads();
        x += y; buf[t] = x; __syncthreads();
    }
    float cum = x, a = ig - cum;
    x = a; buf[t] = x; __syncthreads();
    for (int off = 1; off < 1024; off <<= 1) {
        float y = (t >= off) ? buf[t - off] : -3.4e38f; __syncthreads();
        x = fmaxf(x, y); buf[t] = x; __syncthreads();
    }
    g_a [bh * S_ + t] = a;
    g_rm[bh * S_ + t] = x;
    g_nl[bh * S_ + t] = expf(-(cum + x));
}

// ============== Kernel 3: HMMA fp16 2-term attention, register-prefetch pipeline ==============
#define LDH  136
#define SM_QHI 0
#define SM_KHI 34816
#define SM_KLO 52224
#define SM_VHI 69632
#define SM_VLO 87040
#define SM_RMS 104448      // 128 f32
#define SM_ASB 104960      // 2 x 64 f32
#define SM_WCS 105472      // 2 x 64 f32
#define SM_ERS 105984      // 2 x 128 f32
#define SM_BYTES 107008

__global__ __launch_bounds__(256, 1) void attn_k(
    const float* __restrict__ q, const float* __restrict__ k,
    const float* __restrict__ v, const float* __restrict__ lnsc,
    float* __restrict__ out)
{
    extern __shared__ char smc[];
    const uint32_t smb = (uint32_t)__cvta_generic_to_shared(smc);
    float* rmS = (float*)(smc + SM_RMS);
    float* aSb = (float*)(smc + SM_ASB);   // [2][64]
    float* wcS = (float*)(smc + SM_WCS);   // [2][64]
    float* erS = (float*)(smc + SM_ERS);   // [2][128]

    const int bh = blockIdx.x;
    const int b  = bh >> 4, h = bh & 15;
    const int ri = 7 - (int)blockIdx.y;      // heavy CTAs first
    const int i0 = ri << 7;
    const int t  = threadIdx.x;
    const int w  = t >> 5, lane = t & 31;
    const int gid = lane >> 2, tig = lane & 3;
    const float scale = 0.08838834764831845f;
    const int nj = 2 * ri + 2;

    // fixed per-thread LDG/convert coordinates
    const int ldw = t >> 5;            // base row
    const int ldd = (t & 31) * 4;      // d offset

    auto ldg_tile = [&](const float* base, int j0, float4* reg) {
        const float* p = base + ((size_t)(b * S_ + j0)) * E_ + h * DH_ + ldd;
        #pragma unroll
        for (int it = 0; it < 8; ++it)
            reg[it] = *(const float4*)(p + (size_t)(ldw + it * 8) * E_);
    };
    auto cvstore = [&](const float4* reg, int smHI, int smLO) {
        #pragma unroll
        for (int it = 0; it < 8; ++it) {
            int r = ldw + it * 8;
            uint32_t bo = (uint32_t)(r * LDH + ldd) * 2;
            float4 x = reg[it];
            uint32_t h01 = pack_hf2(x.x, x.y), h23 = pack_hf2(x.z, x.w);
            uint32_t l01 = pack_hf2(x.x - lo_hf(h01), x.y - hi_hf(h01));
            uint32_t l23 = pack_hf2(x.z - lo_hf(h23), x.w - hi_hf(h23));
            *(uint2*)(smc + smHI + bo) = make_uint2(h01, h23);
            *(uint2*)(smc + smLO + bo) = make_uint2(l01, l23);
        }
    };

    // ---- Q staging: fold scale, fp16 hi only; stage aS(0), rmS ----
    {
        const float* qb = q + ((size_t)(b * S_ + i0)) * E_ + h * DH_;
        #pragma unroll
        for (int it = 0; it < 16; ++it) {
            int idx = t + it * 256;
            int r = idx >> 5, d4 = (idx & 31) * 4;
            float4 x = *(const float4*)(qb + (size_t)r * E_ + d4);
            x.x *= scale; x.y *= scale; x.z *= scale; x.w *= scale;
            uint32_t h01 = pack_hf2(x.x, x.y), h23 = pack_hf2(x.z, x.w);
            uint32_t bo = (uint32_t)(r * LDH + d4) * 2;
            *(uint2*)(smc + SM_QHI + bo) = make_uint2(h01, h23);
        }
        if (t < 128) rmS[t] = g_rm[bh * S_ + i0 + t];
        if (t < 64)  aSb[t] = g_a[bh * S_ + t];      // aS for tile 0 into buf 0
    }
    __syncthreads();

    // ---- Q fragments + tables(0) ----
    uint32_t qh[8][4];
    {
        uint32_t rowq = (uint32_t)(w * 16 + (lane & 7) + 8 * ((lane >> 3) & 1));
        #pragma unroll
        for (int kk = 0; kk < 8; ++kk) {
            uint32_t off = (rowq * LDH + kk * 16 + 8 * (lane >> 4)) * 2;
            LDSM4(qh[kk], smb + SM_QHI + off);
        }
    }
    if (t < 128) {
        float m0 = -3.4e38f;
        #pragma unroll 8
        for (int c = 0; c < 64; ++c) m0 = fmaxf(m0, aSb[c]);
        if (t < 64) wcS[t] = __expf(aSb[t] - m0);
        erS[t] = __expf(fminf(m0 - rmS[t], 80.f));
    }

    float hacc[16][4];
    #pragma unroll
    for (int n = 0; n < 16; ++n)
        #pragma unroll
        for (int e = 0; e < 4; ++e) hacc[n][e] = 0.f;
    float suma = 0.f, sumb = 0.f;

    const int rowa = i0 + w * 16 + gid;
    const int rowb = rowa + 8;

    float4 kreg[8], vreg[8];
    ldg_tile(k, 0, kreg);

    #pragma unroll 1
    for (int jt = 0; jt < nj; ++jt) {
        const int j0 = jt << 6;
        const int buf = jt & 1, nbuf = buf ^ 1;

        // phase A: V prefetch for this tile; K(regs) -> smem; aS(jt+1) stage
        ldg_tile(v, j0, vreg);
        cvstore(kreg, SM_KHI, SM_KLO);
        if (t < 64 && jt + 1 < nj) aSb[nbuf * 64 + t] = g_a[bh * S_ + j0 + 64 + t];
        __syncthreads();   // K smem + aS(jt+1) ready; tables(jt) ready from prev iter

        // phase B: QK MMA; tables(jt+1); V(regs) -> smem; mask/exp
        float sacc[8][4];
        #pragma unroll
        for (int n = 0; n < 8; ++n)
            #pragma unroll
            for (int e = 0; e < 4; ++e) sacc[n][e] = 0.f;
        {
            uint32_t rowk = (uint32_t)((lane & 7) + 8 * (lane >> 4));
            uint32_t colk = (uint32_t)(8 * ((lane >> 3) & 1));
            #pragma unroll
            for (int kk = 0; kk < 8; ++kk) {
                #pragma unroll
                for (int np = 0; np < 4; ++np) {
                    uint32_t off = ((np * 16 + rowk) * LDH + kk * 16 + colk) * 2;
                    uint32_t bhf[4], blf[4];
                    LDSM4(bhf, smb + SM_KHI + off);
                    LDSM4(blf, smb + SM_KLO + off);
                    mma16816h(sacc[2 * np],     qh[kk], bhf);
                    mma16816h(sacc[2 * np],     qh[kk], blf);
                    mma16816h(sacc[2 * np + 1], qh[kk], bhf + 2);
                    mma16816h(sacc[2 * np + 1], qh[kk], blf + 2);
                }
            }
        }
        if (t < 128 && jt + 1 < nj) {
            const float* an = aSb + nbuf * 64;
            float m0 = -3.4e38f;
            #pragma unroll 8
            for (int c = 0; c < 64; ++c) m0 = fmaxf(m0, an[c]);
            if (t < 64) wcS[nbuf * 64 + t] = __expf(an[t] - m0);
            erS[nbuf * 128 + t] = __expf(fminf(m0 - rmS[t], 80.f));
        }
        cvstore(vreg, SM_VHI, SM_VLO);

        const float era = erS[buf * 128 + w * 16 + gid];
        const float erb = erS[buf * 128 + w * 16 + gid + 8];
        const float* wcb = wcS + buf * 64;
        #pragma unroll
        for (int n = 0; n < 8; ++n) {
            const int cbase = n * 8 + 2 * tig;
            const int c0 = j0 + cbase, c1 = c0 + 1;
            const float w0 = wcb[cbase], w1 = wcb[cbase + 1];
            float p0 = (c0 <= rowa) ? sacc[n][0] * w0 * era : 0.f;
            float p1 = (c1 <= rowa) ? sacc[n][1] * w1 * era : 0.f;
            float p2 = (c0 <= rowb) ? sacc[n][2] * w0 * erb : 0.f;
            float p3 = (c1 <= rowb) ? sacc[n][3] * w1 * erb : 0.f;
            suma += p0 + p1; sumb += p2 + p3;
            sacc[n][0] = p0; sacc[n][1] = p1; sacc[n][2] = p2; sacc[n][3] = p3;
        }
        __syncthreads();   // V smem ready; all warps past QK (K regs free)

        // phase C: K prefetch for next tile; AV MMA
        if (jt + 1 < nj) ldg_tile(k, j0 + 64, kreg);
        {
            uint32_t rowv = (uint32_t)((lane & 7) + 8 * ((lane >> 3) & 1));
            uint32_t colv = (uint32_t)(8 * (lane >> 4));
            #pragma unroll
            for (int kk = 0; kk < 4; ++kk) {
                uint32_t pah[4];
                pah[0] = pack_hf2(sacc[2*kk][0],   sacc[2*kk][1]);
                pah[1] = pack_hf2(sacc[2*kk][2],   sacc[2*kk][3]);
                pah[2] = pack_hf2(sacc[2*kk+1][0], sacc[2*kk+1][1]);
                pah[3] = pack_hf2(sacc[2*kk+1][2], sacc[2*kk+1][3]);
                #pragma unroll
                for (int np = 0; np < 8; ++np) {
                    uint32_t off = ((kk * 16 + rowv) * LDH + np * 16 + colv) * 2;
                    uint32_t bvh[4], bvl[4];
                    LDSM4T(bvh, smb + SM_VHI + off);
                    LDSM4T(bvl, smb + SM_VLO + off);
                    mma16816h(hacc[2 * np],     pah, bvh);
                    mma16816h(hacc[2 * np],     pah, bvl);
                    mma16816h(hacc[2 * np + 1], pah, bvh + 2);
                    mma16816h(hacc[2 * np + 1], pah, bvl + 2);
                }
            }
        }
    }

    // ---- epilogue ----
    suma += __shfl_xor_sync(0xffffffffu, suma, 1);
    suma += __shfl_xor_sync(0xffffffffu, suma, 2);
    sumb += __shfl_xor_sync(0xffffffffu, sumb, 1);
    sumb += __shfl_xor_sync(0xffffffffu, sumb, 2);
    const float nla = g_nl[bh * S_ + rowa];
    const float nlb = g_nl[bh * S_ + rowb];
    const float inva = 1.f / (fmaxf(fabsf(suma), nla) + EPS_);
    const float invb = 1.f / (fmaxf(fabsf(sumb), nlb) + EPS_);

    float sa = 0.f, sb = 0.f;
    #pragma unroll
    for (int n = 0; n < 16; ++n) {
        sa += hacc[n][0] + hacc[n][1];
        sb += hacc[n][2] + hacc[n][3];
    }
    sa *= inva; sb *= invb;
    sa += __shfl_xor_sync(0xffffffffu, sa, 1);
    sa += __shfl_xor_sync(0xffffffffu, sa, 2);
    sb += __shfl_xor_sync(0xffffffffu, sb, 1);
    sb += __shfl_xor_sync(0xffffffffu, sb, 2);
    const float mua = sa * (1.f / 128.f), mub = sb * (1.f / 128.f);

    float va = 0.f, vbv = 0.f;
    #pragma unroll
    for (int n = 0; n < 16; ++n) {
        float d0 = hacc[n][0] * inva - mua, d1 = hacc[n][1] * inva - mua;
        float d2 = hacc[n][2] * invb - mub, d3 = hacc[n][3] * invb - mub;
        va += d0 * d0 + d1 * d1;
        vbv += d2 * d2 + d3 * d3;
    }
    va += __shfl_xor_sync(0xffffffffu, va, 1);
    va += __shfl_xor_sync(0xffffffffu, va, 2);
    vbv += __shfl_xor_sync(0xffffffffu, vbv, 1);
    vbv += __shfl_xor_sync(0xffffffffu, vbv, 2);
    const float rsa = rsqrtf(va * (1.f / 128.f) + EPS_);
    const float rsb = rsqrtf(vbv * (1.f / 128.f) + EPS_);

    float* outa = out + ((size_t)(b * S_ + rowa)) * E_ + h * DH_;
    float* outb = out + ((size_t)(b * S_ + rowb)) * E_ + h * DH_;
    #pragma unroll
    for (int n = 0; n < 16; ++n) {
        const int d = n * 8 + 2 * tig;
        const float l0 = lnsc[h * DH_ + d], l1 = lnsc[h * DH_ + d + 1];
        float2 oa, ob;
        oa.x = (hacc[n][0] * inva - mua) * rsa * l0;
        oa.y = (hacc[n][1] * inva - mua) * rsa * l1;
        ob.x = (hacc[n][2] * invb - mub) * rsb * l0;
        ob.y = (hacc[n][3] * invb - mub) * rsb * l1;
        *(float2*)(outa + d) = oa;
        *(float2*)(outb + d) = ob;
    }
}

// =====================================================================
extern "C" void kernel_launch(void* const* d_in, const int* in_sizes, int n_in,
                              void* d_out, int out_size)
{
    const float* q  = (const float*)d_in[0];
    const float* k  = (const float*)d_in[1];
    const float* v  = (const float*)d_in[2];
    const float* Wi = (const float*)d_in[3];
    const float* bi = (const float*)d_in[4];
    const float* Wf = (const float*)d_in[5];
    const float* bf = (const float*)d_in[6];
    const float* ln = (const float*)d_in[7];
    float* out = (float*)d_out;

    cudaFuncSetAttribute(attn_k, cudaFuncAttributeMaxDynamicSharedMemorySize, SM_BYTES);

    gates_partial_k<<<dim3(32, NEC), 256>>>(q, k, v, Wi, Wf);
    scan_k<<<B_ * NH_, 1024>>>(bi, bf);
    attn_k<<<dim3(B_ * NH_, 8), 256, SM_BYTES>>>(q, k, v, ln, out);
}

// round 14
// speedup vs baseline: 1.2222x; 1.2222x over previous
#include <cuda_runtime.h>
#include <cuda_fp16.h>
#include <math.h>
#include <stdint.h>

#define B_   2
#define S_   1024
#define E_   2048
#define NH_  16
#define DH_  128
#define EPS_ 1e-6f
#define NEC  24
#define ECH  256          // 6144 / 24, 4 sub-tiles

#define FMA2(d, a, b)  asm("fma.rn.f32x2 %0, %1, %2, %0;" : "+l"(d) : "l"(a), "l"(b))
#define PACK2(d, x)    asm("mov.b64 %0, {%1, %1};" : "=l"(d) : "f"(x))

__device__ __forceinline__ void cpa16(uint32_t dst, const void* src) {
    asm volatile("cp.async.ca.shared.global [%0], [%1], 16;" :: "r"(dst), "l"(src));
}
__device__ __forceinline__ void cpa_commit() { asm volatile("cp.async.commit_group;"); }

// ---------------- warp-MMA helpers (sm_80-era PTX: safe under compute_103) ----------------
static __device__ __forceinline__ uint32_t pack_hf2(float x0, float x1) {
    uint32_t r; asm("cvt.rn.f16x2.f32 %0, %1, %2;" : "=r"(r) : "f"(x1), "f"(x0)); return r;
}

#define LDSM4(r, a) \
    asm volatile("ldmatrix.sync.aligned.m8n8.x4.shared.b16 {%0,%1,%2,%3}, [%4];" \
        : "=r"((r)[0]), "=r"((r)[1]), "=r"((r)[2]), "=r"((r)[3]) : "r"(a))
#define LDSM4T(r, a) \
    asm volatile("ldmatrix.sync.aligned.m8n8.x4.trans.shared.b16 {%0,%1,%2,%3}, [%4];" \
        : "=r"((r)[0]), "=r"((r)[1]), "=r"((r)[2]), "=r"((r)[3]) : "r"(a))

static __device__ __forceinline__ void mma16816h(float* c, const uint32_t* a, const uint32_t* b) {
    asm volatile("mma.sync.aligned.m16n8k16.row.col.f32.f16.f16.f32 "
        "{%0,%1,%2,%3}, {%4,%5,%6,%7}, {%8,%9}, {%0,%1,%2,%3};"
        : "+f"(c[0]), "+f"(c[1]), "+f"(c[2]), "+f"(c[3])
        : "r"(a[0]), "r"(a[1]), "r"(a[2]), "r"(a[3]), "r"(b[0]), "r"(b[1]));
}

__device__ float g_part[2 * NEC * B_ * NH_ * S_];
__device__ float g_a [B_ * NH_ * S_];
__device__ float g_rm[B_ * NH_ * S_];
__device__ float g_nl[B_ * NH_ * S_];

// ============== Kernel 1: gates (R13 version, measured 40.9us) ==============
__global__ __launch_bounds__(256, 3) void gates_partial_k(
    const float* __restrict__ q, const float* __restrict__ k, const float* __restrict__ v,
    const float* __restrict__ Wi, const float* __restrict__ Wf)
{
    __shared__ float Xs[2][64 * 68];
    __shared__ float Ws[2][64 * 32];
    const int rt = blockIdx.x, ec = blockIdx.y;
    const int b = rt >> 4, s0 = (rt & 15) << 6, t = threadIdx.x;
    const int rgrp = t >> 3, hgrp = t & 7;

    auto pf = [&](int sub, int bufi) {
        const int e0 = ec * ECH + sub * 64;
        const float* xp = (e0 < E_) ? q : (e0 < 2 * E_) ? k : v;
        const int col0 = e0 & (E_ - 1);
        float* xd = Xs[bufi];
        float* wd = Ws[bufi];
        #pragma unroll
        for (int c = 0; c < 4; ++c) {
            int idx = t + c * 256, r = idx >> 4, q4 = (idx & 15) * 4;
            cpa16((uint32_t)__cvta_generic_to_shared(xd + r * 68 + q4),
                  xp + ((size_t)(b * S_ + s0 + r)) * E_ + col0 + q4);
        }
        #pragma unroll
        for (int c = 0; c < 2; ++c) {
            int idx = t + c * 256, ee = idx >> 3, cc = idx & 7, eg = e0 + ee;
            const float* src = (cc < 4) ? (Wi + eg * 16 + cc * 4)
                                        : (Wf + eg * 16 + (cc - 4) * 4);
            cpa16((uint32_t)__cvta_generic_to_shared(wd + ee * 32 + cc * 4), src);
        }
        cpa_commit();
    };

    unsigned long long acc2[2][2] = {};
    pf(0, 0);
    #pragma unroll 1
    for (int sub = 0; sub < 4; ++sub) {
        const int bufi = sub & 1;
        if (sub < 3) {
            pf(sub + 1, bufi ^ 1);
            asm volatile("cp.async.wait_group 1;");
        } else {
            asm volatile("cp.async.wait_group 0;");
        }
        __syncthreads();
        const float* xs = Xs[bufi];
        const float* ws = Ws[bufi];
        #pragma unroll 8
        for (int ee = 0; ee < 64; ++ee) {
            unsigned long long xp2[2];
            #pragma unroll
            for (int m = 0; m < 2; ++m) { float xv = xs[(rgrp * 2 + m) * 68 + ee]; PACK2(xp2[m], xv); }
            ulonglong2 wv = *(const ulonglong2*)(ws + ee * 32 + hgrp * 4);
            #pragma unroll
            for (int m = 0; m < 2; ++m) { FMA2(acc2[m][0], xp2[m], wv.x); FMA2(acc2[m][1], xp2[m], wv.y); }
        }
        __syncthreads();
    }
    #pragma unroll
    for (int m = 0; m < 2; ++m) {
        int s = s0 + rgrp * 2 + m;
        #pragma unroll
        for (int p = 0; p < 2; ++p) {
            float2 u = *(float2*)&acc2[m][p];
            #pragma unroll
            for (int hh = 0; hh < 2; ++hh) {
                int hcol = hgrp * 4 + p * 2 + hh;
                g_part[(((hcol >> 4) * NEC + ec) * (B_ * NH_) + b * NH_ + (hcol & 15)) * S_ + s] = hh ? u.y : u.x;
            }
        }
    }
}

// ============== Kernel 2: scans ==============
__global__ __launch_bounds__(1024, 1) void scan_k(const float* __restrict__ bi, const float* __restrict__ bf)
{
    __shared__ float buf[1024];
    const int bh = blockIdx.x, t = threadIdx.x, h = bh & 15;
    float ig = bi[h], fg = bf[h];
    #pragma unroll
    for (int ec = 0; ec < NEC; ++ec) {
        ig += g_part[((0 * NEC + ec) * (B_ * NH_) + bh) * S_ + t];
        fg += g_part[((1 * NEC + ec) * (B_ * NH_) + bh) * S_ + t];
    }
    float lf = fminf(fg, 0.f) - log1pf(expf(-fabsf(fg)));
    float x = lf;
    buf[t] = x; __syncthreads();
    for (int off = 1; off < 1024; off <<= 1) {
        float y = (t >= off) ? buf[t - off] : 0.f; __syncthreads();
        x += y; buf[t] = x; __syncthreads();
    }
    float cum = x, a = ig - cum;
    x = a; buf[t] = x; __syncthreads();
    for (int off = 1; off < 1024; off <<= 1) {
        float y = (t >= off) ? buf[t - off] : -3.4e38f; __syncthreads();
        x = fmaxf(x, y); buf[t] = x; __syncthreads();
    }
    g_a [bh * S_ + t] = a;
    g_rm[bh * S_ + t] = x;
    g_nl[bh * S_ + t] = expf(-(cum + x));
}

// ============== Kernel 3: HMMA plain-fp16 attention (single-term) ==============
#define LDH  136
#define SM_QHI 0
#define SM_KHI 34816
#define SM_VHI 52224
#define SM_AS  69632
#define SM_RMS 69888
#define SM_ERS 70400
#define SM_WCS 70912
#define SM_BYTES 71168

__global__ __launch_bounds__(256, 1) void attn_k(
    const float* __restrict__ q, const float* __restrict__ k,
    const float* __restrict__ v, const float* __restrict__ lnsc,
    float* __restrict__ out)
{
    extern __shared__ char smc[];
    const uint32_t smb = (uint32_t)__cvta_generic_to_shared(smc);
    float* aS  = (float*)(smc + SM_AS);
    float* rmS = (float*)(smc + SM_RMS);
    float* erS = (float*)(smc + SM_ERS);
    float* wcS = (float*)(smc + SM_WCS);

    const int bh = blockIdx.x;
    const int b  = bh >> 4, h = bh & 15;
    const int ri = 7 - (int)blockIdx.y;      // heavy CTAs first
    const int i0 = ri << 7;
    const int t  = threadIdx.x;
    const int w  = t >> 5, lane = t & 31;
    const int gid = lane >> 2, tig = lane & 3;
    const float scale = 0.08838834764831845f;

    // ---- Q load: fold scale, fp16 into padded row-major smem ----
    {
        const float* qb = q + ((size_t)(b * S_ + i0)) * E_ + h * DH_;
        #pragma unroll
        for (int it = 0; it < 16; ++it) {
            int idx = t + it * 256;
            int r = idx >> 5, d4 = (idx & 31) * 4;
            float4 x = *(const float4*)(qb + (size_t)r * E_ + d4);
            x.x *= scale; x.y *= scale; x.z *= scale; x.w *= scale;
            uint32_t h01 = pack_hf2(x.x, x.y), h23 = pack_hf2(x.z, x.w);
            uint32_t bo = (uint32_t)(r * LDH + d4) * 2;
            *(uint2*)(smc + SM_QHI + bo) = make_uint2(h01, h23);
        }
        if (t < 128) rmS[t] = g_rm[bh * S_ + i0 + t];
    }
    __syncthreads();

    // ---- cache Q fragments in registers (A-operand layout) ----
    uint32_t qh[8][4];
    {
        uint32_t rowq = (uint32_t)(w * 16 + (lane & 7) + 8 * ((lane >> 3) & 1));
        #pragma unroll
        for (int kk = 0; kk < 8; ++kk) {
            uint32_t off = (rowq * LDH + kk * 16 + 8 * (lane >> 4)) * 2;
            LDSM4(qh[kk], smb + SM_QHI + off);
        }
    }

    float hacc[16][4];
    #pragma unroll
    for (int n = 0; n < 16; ++n)
        #pragma unroll
        for (int e = 0; e < 4; ++e) hacc[n][e] = 0.f;
    float suma = 0.f, sumb = 0.f;

    const int rowa = i0 + w * 16 + gid;
    const int rowb = rowa + 8;
    const int nj = 2 * ri + 2;

    for (int jt = 0; jt < nj; ++jt) {
        const int j0 = jt << 6;
        __syncthreads();    // prev tile compute done before overwriting K/V/tables
        // ---- K,V tiles: fp16 ----
        {
            const float* kb = k + ((size_t)(b * S_ + j0)) * E_ + h * DH_;
            const float* vb = v + ((size_t)(b * S_ + j0)) * E_ + h * DH_;
            #pragma unroll
            for (int it = 0; it < 8; ++it) {
                int idx = t + it * 256;
                int r = idx >> 5, d4 = (idx & 31) * 4;
                uint32_t bo = (uint32_t)(r * LDH + d4) * 2;
                float4 x = *(const float4*)(kb + (size_t)r * E_ + d4);
                *(uint2*)(smc + SM_KHI + bo) = make_uint2(pack_hf2(x.x, x.y), pack_hf2(x.z, x.w));
                float4 y = *(const float4*)(vb + (size_t)r * E_ + d4);
                *(uint2*)(smc + SM_VHI + bo) = make_uint2(pack_hf2(y.x, y.y), pack_hf2(y.z, y.w));
            }
            if (t < 64) aS[t] = g_a[bh * S_ + j0 + t];
        }
        __syncthreads();
        // ---- exp tables ----
        if (t < 128) {
            float m0 = -3.4e38f;
            #pragma unroll 8
            for (int c = 0; c < 64; ++c) m0 = fmaxf(m0, aS[c]);
            if (t < 64) wcS[t] = __expf(aS[t] - m0);
            erS[t] = __expf(fminf(m0 - rmS[t], 80.f));
        }
        __syncthreads();

        // ---- QK: S = Q K^T ----
        float sacc[8][4];
        #pragma unroll
        for (int n = 0; n < 8; ++n)
            #pragma unroll
            for (int e = 0; e < 4; ++e) sacc[n][e] = 0.f;
        {
            uint32_t rowk = (uint32_t)((lane & 7) + 8 * (lane >> 4));
            uint32_t colk = (uint32_t)(8 * ((lane >> 3) & 1));
            #pragma unroll
            for (int kk = 0; kk < 8; ++kk) {
                #pragma unroll
                for (int np = 0; np < 4; ++np) {
                    uint32_t off = ((np * 16 + rowk) * LDH + kk * 16 + colk) * 2;
                    uint32_t bhf[4];
                    LDSM4(bhf, smb + SM_KHI + off);
                    mma16816h(sacc[2 * np],     qh[kk], bhf);
                    mma16816h(sacc[2 * np + 1], qh[kk], bhf + 2);
                }
            }
        }

        // ---- S -> P, causal mask, rowsums ----
        const float era = erS[w * 16 + gid];
        const float erb = erS[w * 16 + gid + 8];
        #pragma unroll
        for (int n = 0; n < 8; ++n) {
            const int cbase = n * 8 + 2 * tig;
            const int c0 = j0 + cbase, c1 = c0 + 1;
            const float w0 = wcS[cbase], w1 = wcS[cbase + 1];
            float p0 = (c0 <= rowa) ? sacc[n][0] * w0 * era : 0.f;
            float p1 = (c1 <= rowa) ? sacc[n][1] * w1 * era : 0.f;
            float p2 = (c0 <= rowb) ? sacc[n][2] * w0 * erb : 0.f;
            float p3 = (c1 <= rowb) ? sacc[n][3] * w1 * erb : 0.f;
            suma += p0 + p1; sumb += p2 + p3;
            sacc[n][0] = p0; sacc[n][1] = p1; sacc[n][2] = p2; sacc[n][3] = p3;
        }

        // ---- AV: H += P V ----
        {
            uint32_t rowv = (uint32_t)((lane & 7) + 8 * ((lane >> 3) & 1));
            uint32_t colv = (uint32_t)(8 * (lane >> 4));
            #pragma unroll
            for (int kk = 0; kk < 4; ++kk) {
                uint32_t pah[4];
                pah[0] = pack_hf2(sacc[2*kk][0],   sacc[2*kk][1]);
                pah[1] = pack_hf2(sacc[2*kk][2],   sacc[2*kk][3]);
                pah[2] = pack_hf2(sacc[2*kk+1][0], sacc[2*kk+1][1]);
                pah[3] = pack_hf2(sacc[2*kk+1][2], sacc[2*kk+1][3]);
                #pragma unroll
                for (int np = 0; np < 8; ++np) {
                    uint32_t off = ((kk * 16 + rowv) * LDH + np * 16 + colv) * 2;
                    uint32_t bvh[4];
                    LDSM4T(bvh, smb + SM_VHI + off);
                    mma16816h(hacc[2 * np],     pah, bvh);
                    mma16816h(hacc[2 * np + 1], pah, bvh + 2);
                }
            }
        }
    }

    // ---- epilogue ----
    suma += __shfl_xor_sync(0xffffffffu, suma, 1);
    suma += __shfl_xor_sync(0xffffffffu, suma, 2);
    sumb += __shfl_xor_sync(0xffffffffu, sumb, 1);
    sumb += __shfl_xor_sync(0xffffffffu, sumb, 2);
    const float nla = g_nl[bh * S_ + rowa];
    const float nlb = g_nl[bh * S_ + rowb];
    const float inva = 1.f / (fmaxf(fabsf(suma), nla) + EPS_);
    const float invb = 1.f / (fmaxf(fabsf(sumb), nlb) + EPS_);

    float sa = 0.f, sb = 0.f;
    #pragma unroll
    for (int n = 0; n < 16; ++n) {
        sa += hacc[n][0] + hacc[n][1];
        sb += hacc[n][2] + hacc[n][3];
    }
    sa *= inva; sb *= invb;
    sa += __shfl_xor_sync(0xffffffffu, sa, 1);
    sa += __shfl_xor_sync(0xffffffffu, sa, 2);
    sb += __shfl_xor_sync(0xffffffffu, sb, 1);
    sb += __shfl_xor_sync(0xffffffffu, sb, 2);
    const float mua = sa * (1.f / 128.f), mub = sb * (1.f / 128.f);

    float va = 0.f, vbv = 0.f;
    #pragma unroll
    for (int n = 0; n < 16; ++n) {
        float d0 = hacc[n][0] * inva - mua, d1 = hacc[n][1] * inva - mua;
        float d2 = hacc[n][2] * invb - mub, d3 = hacc[n][3] * invb - mub;
        va += d0 * d0 + d1 * d1;
        vbv += d2 * d2 + d3 * d3;
    }
    va += __shfl_xor_sync(0xffffffffu, va, 1);
    va += __shfl_xor_sync(0xffffffffu, va, 2);
    vbv += __shfl_xor_sync(0xffffffffu, vbv, 1);
    vbv += __shfl_xor_sync(0xffffffffu, vbv, 2);
    const float rsa = rsqrtf(va * (1.f / 128.f) + EPS_);
    const float rsb = rsqrtf(vbv * (1.f / 128.f) + EPS_);

    float* outa = out + ((size_t)(b * S_ + rowa)) * E_ + h * DH_;
    float* outb = out + ((size_t)(b * S_ + rowb)) * E_ + h * DH_;
    #pragma unroll
    for (int n = 0; n < 16; ++n) {
        const int d = n * 8 + 2 * tig;
        const float l0 = lnsc[h * DH_ + d], l1 = lnsc[h * DH_ + d + 1];
        float2 oa, ob;
        oa.x = (hacc[n][0] * inva - mua) * rsa * l0;
        oa.y = (hacc[n][1] * inva - mua) * rsa * l1;
        ob.x = (hacc[n][2] * invb - mub) * rsb * l0;
        ob.y = (hacc[n][3] * invb - mub) * rsb * l1;
        *(float2*)(outa + d) = oa;
        *(float2*)(outb + d) = ob;
    }
}

// =====================================================================
extern "C" void kernel_launch(void* const* d_in, const int* in_sizes, int n_in,
                              void* d_out, int out_size)
{
    const float* q  = (const float*)d_in[0];
    const float* k  = (const float*)d_in[1];
    const float* v  = (const float*)d_in[2];
    const float* Wi = (const float*)d_in[3];
    const float* bi = (const float*)d_in[4];
    const float* Wf = (const float*)d_in[5];
    const float* bf = (const float*)d_in[6];
    const float* ln = (const float*)d_in[7];
    float* out = (float*)d_out;

    cudaFuncSetAttribute(attn_k, cudaFuncAttributeMaxDynamicSharedMemorySize, SM_BYTES);

    gates_partial_k<<<dim3(32, NEC), 256>>>(q, k, v, Wi, Wf);
    scan_k<<<B_ * NH_, 1024>>>(bi, bf);
    attn_k<<<dim3(B_ * NH_, 8), 256, SM_BYTES>>>(q, k, v, ln, out);
}

// round 15
// speedup vs baseline: 1.4560x; 1.1913x over previous
#include <cuda_runtime.h>
#include <cuda_fp16.h>
#include <math.h>
#include <stdint.h>

#define B_   2
#define S_   1024
#define E_   2048
#define NH_  16
#define DH_  128
#define EPS_ 1e-6f
#define NEC  24
#define ECH  256          // 6144 / 24, 4 sub-stages of 64

// ---------------- warp-MMA helpers (sm_80-era PTX: safe under compute_103) ----------------
static __device__ __forceinline__ uint32_t pack_hf2(float x0, float x1) {
    uint32_t r; asm("cvt.rn.f16x2.f32 %0, %1, %2;" : "=r"(r) : "f"(x1), "f"(x0)); return r;
}
static __device__ __forceinline__ uint32_t pack_bf2(float x0, float x1) {
    uint32_t r; asm("cvt.rn.bf16x2.f32 %0, %1, %2;" : "=r"(r) : "f"(x1), "f"(x0)); return r;
}
static __device__ __forceinline__ float lo_bf(uint32_t p) { return __uint_as_float(p << 16); }
static __device__ __forceinline__ float hi_bf(uint32_t p) { return __uint_as_float(p & 0xffff0000u); }

#define LDSM4(r, a) \
    asm volatile("ldmatrix.sync.aligned.m8n8.x4.shared.b16 {%0,%1,%2,%3}, [%4];" \
        : "=r"((r)[0]), "=r"((r)[1]), "=r"((r)[2]), "=r"((r)[3]) : "r"(a))
#define LDSM4T(r, a) \
    asm volatile("ldmatrix.sync.aligned.m8n8.x4.trans.shared.b16 {%0,%1,%2,%3}, [%4];" \
        : "=r"((r)[0]), "=r"((r)[1]), "=r"((r)[2]), "=r"((r)[3]) : "r"(a))

static __device__ __forceinline__ void mma16816h(float* c, const uint32_t* a, const uint32_t* b) {
    asm volatile("mma.sync.aligned.m16n8k16.row.col.f32.f16.f16.f32 "
        "{%0,%1,%2,%3}, {%4,%5,%6,%7}, {%8,%9}, {%0,%1,%2,%3};"
        : "+f"(c[0]), "+f"(c[1]), "+f"(c[2]), "+f"(c[3])
        : "r"(a[0]), "r"(a[1]), "r"(a[2]), "r"(a[3]), "r"(b[0]), "r"(b[1]));
}
static __device__ __forceinline__ void mma16816b(float* c, const uint32_t* a, const uint32_t* b) {
    asm volatile("mma.sync.aligned.m16n8k16.row.col.f32.bf16.bf16.f32 "
        "{%0,%1,%2,%3}, {%4,%5,%6,%7}, {%8,%9}, {%0,%1,%2,%3};"
        : "+f"(c[0]), "+f"(c[1]), "+f"(c[2]), "+f"(c[3])
        : "r"(a[0]), "r"(a[1]), "r"(a[2]), "r"(a[3]), "r"(b[0]), "r"(b[1]));
}

__device__ float g_part[2 * NEC * B_ * NH_ * S_];
__device__ float g_a [B_ * NH_ * S_];
__device__ float g_rm[B_ * NH_ * S_];
__device__ float g_nl[B_ * NH_ * S_];

// ============== Kernel 1: gates, bf16 3-term HMMA ==============
// smem halves-stride 72 (144B rows: 16B-aligned, +4 banks/row -> conflict-free LDSM)
#define GLD 72

__global__ __launch_bounds__(256) void gates_partial_k(
    const float* __restrict__ q, const float* __restrict__ k, const float* __restrict__ v,
    const float* __restrict__ Wi, const float* __restrict__ Wf)
{
    __shared__ __align__(16) unsigned short XsH[64 * GLD], XsL[64 * GLD];
    __shared__ __align__(16) unsigned short WsH[32 * GLD], WsL[32 * GLD];

    const int rt = blockIdx.x, ec = blockIdx.y;
    const int b = rt >> 4, s0 = (rt & 15) << 6, t = threadIdx.x;
    const int w = t >> 5, lane = t & 31;
    const int rw = w & 3;            // row-group (16 rows)
    const int kh = w >> 1 >> 1;      // 0 for warps 0-3, 1 for warps 4-7 (ee half)
    const uint32_t xhB = (uint32_t)__cvta_generic_to_shared(XsH);
    const uint32_t xlB = (uint32_t)__cvta_generic_to_shared(XsL);
    const uint32_t whB = (uint32_t)__cvta_generic_to_shared(WsH);
    const uint32_t wlB = (uint32_t)__cvta_generic_to_shared(WsL);

    float acc[4][4];
    #pragma unroll
    for (int j = 0; j < 4; ++j)
        #pragma unroll
        for (int e = 0; e < 4; ++e) acc[j][e] = 0.f;

    #pragma unroll 1
    for (int sub = 0; sub < 4; ++sub) {
        const int e0 = ec * ECH + sub * 64;
        const float* xp = (e0 < E_) ? q : (e0 < 2 * E_) ? k : v;
        const int col0 = e0 & (E_ - 1);
        __syncthreads();   // prev MMA reads done
        // ---- stage X (64 rows x 64 ee): bf16 hi/lo ----
        #pragma unroll
        for (int it = 0; it < 4; ++it) {
            int idx = t + it * 256;
            int r = idx >> 4, c4 = (idx & 15) * 4;
            float4 x = *(const float4*)(xp + ((size_t)(b * S_ + s0 + r)) * E_ + col0 + c4);
            uint32_t h01 = pack_bf2(x.x, x.y), h23 = pack_bf2(x.z, x.w);
            uint32_t l01 = pack_bf2(x.x - lo_bf(h01), x.y - hi_bf(h01));
            uint32_t l23 = pack_bf2(x.z - lo_bf(h23), x.w - hi_bf(h23));
            *(uint2*)((char*)XsH + (r * GLD + c4) * 2) = make_uint2(h01, h23);
            *(uint2*)((char*)XsL + (r * GLD + c4) * 2) = make_uint2(l01, l23);
        }
        // ---- stage W transposed [hcol][ee] (64 ee x 32 cols): bf16 hi/lo ----
        #pragma unroll
        for (int it = 0; it < 2; ++it) {
            int idx = t + it * 256;
            int ee = idx >> 3, cc = idx & 7;
            int eg = e0 + ee;
            float4 wv = (cc < 4) ? *(const float4*)(Wi + eg * 16 + cc * 4)
                                 : *(const float4*)(Wf + eg * 16 + (cc - 4) * 4);
            const float wj[4] = {wv.x, wv.y, wv.z, wv.w};
            #pragma unroll
            for (int j = 0; j < 4; ++j) {
                int hcol = cc * 4 + j;   // 0..15 Wi, 16..31 Wf
                uint32_t p = pack_bf2(wj[j], 0.f);
                float hif = lo_bf(p);
                uint32_t pl = pack_bf2(wj[j] - hif, 0.f);
                WsH[hcol * GLD + ee] = (unsigned short)(p & 0xffffu);
                WsL[hcol * GLD + ee] = (unsigned short)(pl & 0xffffu);
            }
        }
        __syncthreads();
        // ---- MMA: warp = rows rw*16..+15, ee-half kh, 2 ksteps ----
        {
            const uint32_t rowa = (uint32_t)(rw * 16 + (lane & 15));
            const uint32_t asel = (uint32_t)((lane >> 4) * 8);
            const uint32_t rowk = (uint32_t)((lane & 7) + 8 * (lane >> 4));
            const uint32_t colk = (uint32_t)(8 * ((lane >> 3) & 1));
            #pragma unroll
            for (int ks = 0; ks < 2; ++ks) {
                const int kk = kh * 2 + ks;
                uint32_t aoff = (rowa * GLD + kk * 16 + asel) * 2;
                uint32_t ah[4], al[4];
                LDSM4(ah, xhB + aoff);
                LDSM4(al, xlB + aoff);
                uint32_t bh0[4], bh1[4], bl0[4], bl1[4];
                uint32_t boff0 = ((0 * 16 + rowk) * GLD + kk * 16 + colk) * 2;
                uint32_t boff1 = ((1 * 16 + rowk) * GLD + kk * 16 + colk) * 2;
                LDSM4(bh0, whB + boff0);
                LDSM4(bh1, whB + boff1);
                LDSM4(bl0, wlB + boff0);
                LDSM4(bl1, wlB + boff1);
                mma16816b(acc[0], ah, bh0);     mma16816b(acc[0], ah, bl0);     mma16816b(acc[0], al, bh0);
                mma16816b(acc[1], ah, bh0 + 2); mma16816b(acc[1], ah, bl0 + 2); mma16816b(acc[1], al, bh0 + 2);
                mma16816b(acc[2], ah, bh1);     mma16816b(acc[2], ah, bl1);     mma16816b(acc[2], al, bh1);
                mma16816b(acc[3], ah, bh1 + 2); mma16816b(acc[3], ah, bl1 + 2); mma16816b(acc[3], al, bh1 + 2);
            }
        }
    }

    // ---- cross-warp reduce (ee halves) + write g_part ----
    __syncthreads();
    float* red = (float*)XsH;   // 4 warps x 32 lanes x 16 f32 = 8KB <= XsH size
    if (kh == 1) {
        float* dst = red + ((w - 4) * 32 + lane) * 16;
        #pragma unroll
        for (int j = 0; j < 4; ++j)
            #pragma unroll
            for (int e = 0; e < 4; ++e) dst[j * 4 + e] = acc[j][e];
    }
    __syncthreads();
    if (kh == 0) {
        const float* src = red + (w * 32 + lane) * 16;
        #pragma unroll
        for (int j = 0; j < 4; ++j)
            #pragma unroll
            for (int e = 0; e < 4; ++e) acc[j][e] += src[j * 4 + e];
        // C frag: e0: (row lane>>2, col 2*(lane&3)), e1 col+1, e2 row+8, e3 row+8 col+1
        const int r0 = s0 + rw * 16 + (lane >> 2);
        #pragma unroll
        for (int j = 0; j < 4; ++j) {
            #pragma unroll
            for (int e = 0; e < 4; ++e) {
                int s  = r0 + (e >> 1) * 8;
                int hcol = j * 8 + 2 * (lane & 3) + (e & 1);
                int gate = hcol >> 4, hm = hcol & 15;
                g_part[((gate * NEC + ec) * (B_ * NH_) + b * NH_ + hm) * S_ + s] = acc[j][e];
            }
        }
    }
}

// ============== Kernel 2: scans (unchanged) ==============
__global__ __launch_bounds__(1024, 1) void scan_k(const float* __restrict__ bi, const float* __restrict__ bf)
{
    __shared__ float buf[1024];
    const int bh = blockIdx.x, t = threadIdx.x, h = bh & 15;
    float ig = bi[h], fg = bf[h];
    #pragma unroll
    for (int ec = 0; ec < NEC; ++ec) {
        ig += g_part[((0 * NEC + ec) * (B_ * NH_) + bh) * S_ + t];
        fg += g_part[((1 * NEC + ec) * (B_ * NH_) + bh) * S_ + t];
    }
    float lf = fminf(fg, 0.f) - log1pf(expf(-fabsf(fg)));
    float x = lf;
    buf[t] = x; __syncthreads();
    for (int off = 1; off < 1024; off <<= 1) {
        float y = (t >= off) ? buf[t - off] : 0.f; __syncthreads();
        x += y; buf[t] = x; __syncthreads();
    }
    float cum = x, a = ig - cum;
    x = a; buf[t] = x; __syncthreads();
    for (int off = 1; off < 1024; off <<= 1) {
        float y = (t >= off) ? buf[t - off] : -3.4e38f; __syncthreads();
        x = fmaxf(x, y); buf[t] = x; __syncthreads();
    }
    g_a [bh * S_ + t] = a;
    g_rm[bh * S_ + t] = x;
    g_nl[bh * S_ + t] = expf(-(cum + x));
}

// ============== Kernel 3: HMMA plain-fp16 attention (R14, measured ~45us) ==============
#define LDH  136
#define SM_QHI 0
#define SM_KHI 34816
#define SM_VHI 52224
#define SM_AS  69632
#define SM_RMS 69888
#define SM_ERS 70400
#define SM_WCS 70912
#define SM_BYTES 71168

__global__ __launch_bounds__(256, 1) void attn_k(
    const float* __restrict__ q, const float* __restrict__ k,
    const float* __restrict__ v, const float* __restrict__ lnsc,
    float* __restrict__ out)
{
    extern __shared__ char smc[];
    const uint32_t smb = (uint32_t)__cvta_generic_to_shared(smc);
    float* aS  = (float*)(smc + SM_AS);
    float* rmS = (float*)(smc + SM_RMS);
    float* erS = (float*)(smc + SM_ERS);
    float* wcS = (float*)(smc + SM_WCS);

    const int bh = blockIdx.x;
    const int b  = bh >> 4, h = bh & 15;
    const int ri = 7 - (int)blockIdx.y;      // heavy CTAs first
    const int i0 = ri << 7;
    const int t  = threadIdx.x;
    const int w  = t >> 5, lane = t & 31;
    const int gid = lane >> 2, tig = lane & 3;
    const float scale = 0.08838834764831845f;

    // ---- Q load: fold scale, fp16 into padded row-major smem ----
    {
        const float* qb = q + ((size_t)(b * S_ + i0)) * E_ + h * DH_;
        #pragma unroll
        for (int it = 0; it < 16; ++it) {
            int idx = t + it * 256;
            int r = idx >> 5, d4 = (idx & 31) * 4;
            float4 x = *(const float4*)(qb + (size_t)r * E_ + d4);
            x.x *= scale; x.y *= scale; x.z *= scale; x.w *= scale;
            uint32_t h01 = pack_hf2(x.x, x.y), h23 = pack_hf2(x.z, x.w);
            uint32_t bo = (uint32_t)(r * LDH + d4) * 2;
            *(uint2*)(smc + SM_QHI + bo) = make_uint2(h01, h23);
        }
        if (t < 128) rmS[t] = g_rm[bh * S_ + i0 + t];
    }
    __syncthreads();

    // ---- cache Q fragments in registers (A-operand layout) ----
    uint32_t qh[8][4];
    {
        uint32_t rowq = (uint32_t)(w * 16 + (lane & 7) + 8 * ((lane >> 3) & 1));
        #pragma unroll
        for (int kk = 0; kk < 8; ++kk) {
            uint32_t off = (rowq * LDH + kk * 16 + 8 * (lane >> 4)) * 2;
            LDSM4(qh[kk], smb + SM_QHI + off);
        }
    }

    float hacc[16][4];
    #pragma unroll
    for (int n = 0; n < 16; ++n)
        #pragma unroll
        for (int e = 0; e < 4; ++e) hacc[n][e] = 0.f;
    float suma = 0.f, sumb = 0.f;

    const int rowa = i0 + w * 16 + gid;
    const int rowb = rowa + 8;
    const int nj = 2 * ri + 2;

    for (int jt = 0; jt < nj; ++jt) {
        const int j0 = jt << 6;
        __syncthreads();    // prev tile compute done before overwriting K/V/tables
        // ---- K,V tiles: fp16 ----
        {
            const float* kb = k + ((size_t)(b * S_ + j0)) * E_ + h * DH_;
            const float* vb = v + ((size_t)(b * S_ + j0)) * E_ + h * DH_;
            #pragma unroll
            for (int it = 0; it < 8; ++it) {
                int idx = t + it * 256;
                int r = idx >> 5, d4 = (idx & 31) * 4;
                uint32_t bo = (uint32_t)(r * LDH + d4) * 2;
                float4 x = *(const float4*)(kb + (size_t)r * E_ + d4);
                *(uint2*)(smc + SM_KHI + bo) = make_uint2(pack_hf2(x.x, x.y), pack_hf2(x.z, x.w));
                float4 y = *(const float4*)(vb + (size_t)r * E_ + d4);
                *(uint2*)(smc + SM_VHI + bo) = make_uint2(pack_hf2(y.x, y.y), pack_hf2(y.z, y.w));
            }
            if (t < 64) aS[t] = g_a[bh * S_ + j0 + t];
        }
        __syncthreads();
        // ---- exp tables ----
        if (t < 128) {
            float m0 = -3.4e38f;
            #pragma unroll 8
            for (int c = 0; c < 64; ++c) m0 = fmaxf(m0, aS[c]);
            if (t < 64) wcS[t] = __expf(aS[t] - m0);
            erS[t] = __expf(fminf(m0 - rmS[t], 80.f));
        }
        __syncthreads();

        // ---- QK: S = Q K^T ----
        float sacc[8][4];
        #pragma unroll
        for (int n = 0; n < 8; ++n)
            #pragma unroll
            for (int e = 0; e < 4; ++e) sacc[n][e] = 0.f;
        {
            uint32_t rowk = (uint32_t)((lane & 7) + 8 * (lane >> 4));
            uint32_t colk = (uint32_t)(8 * ((lane >> 3) & 1));
            #pragma unroll
            for (int kk = 0; kk < 8; ++kk) {
                #pragma unroll
                for (int np = 0; np < 4; ++np) {
                    uint32_t off = ((np * 16 + rowk) * LDH + kk * 16 + colk) * 2;
                    uint32_t bhf[4];
                    LDSM4(bhf, smb + SM_KHI + off);
                    mma16816h(sacc[2 * np],     qh[kk], bhf);
                    mma16816h(sacc[2 * np + 1], qh[kk], bhf + 2);
                }
            }
        }

        // ---- S -> P, causal mask, rowsums ----
        const float era = erS[w * 16 + gid];
        const float erb = erS[w * 16 + gid + 8];
        #pragma unroll
        for (int n = 0; n < 8; ++n) {
            const int cbase = n * 8 + 2 * tig;
            const int c0 = j0 + cbase, c1 = c0 + 1;
            const float w0 = wcS[cbase], w1 = wcS[cbase + 1];
            float p0 = (c0 <= rowa) ? sacc[n][0] * w0 * era : 0.f;
            float p1 = (c1 <= rowa) ? sacc[n][1] * w1 * era : 0.f;
            float p2 = (c0 <= rowb) ? sacc[n][2] * w0 * erb : 0.f;
            float p3 = (c1 <= rowb) ? sacc[n][3] * w1 * erb : 0.f;
            suma += p0 + p1; sumb += p2 + p3;
            sacc[n][0] = p0; sacc[n][1] = p1; sacc[n][2] = p2; sacc[n][3] = p3;
        }

        // ---- AV: H += P V ----
        {
            uint32_t rowv = (uint32_t)((lane & 7) + 8 * ((lane >> 3) & 1));
            uint32_t colv = (uint32_t)(8 * (lane >> 4));
            #pragma unroll
            for (int kk = 0; kk < 4; ++kk) {
                uint32_t pah[4];
                pah[0] = pack_hf2(sacc[2*kk][0],   sacc[2*kk][1]);
                pah[1] = pack_hf2(sacc[2*kk][2],   sacc[2*kk][3]);
                pah[2] = pack_hf2(sacc[2*kk+1][0], sacc[2*kk+1][1]);
                pah[3] = pack_hf2(sacc[2*kk+1][2], sacc[2*kk+1][3]);
                #pragma unroll
                for (int np = 0; np < 8; ++np) {
                    uint32_t off = ((kk * 16 + rowv) * LDH + np * 16 + colv) * 2;
                    uint32_t bvh[4];
                    LDSM4T(bvh, smb + SM_VHI + off);
                    mma16816h(hacc[2 * np],     pah, bvh);
                    mma16816h(hacc[2 * np + 1], pah, bvh + 2);
                }
            }
        }
    }

    // ---- epilogue ----
    suma += __shfl_xor_sync(0xffffffffu, suma, 1);
    suma += __shfl_xor_sync(0xffffffffu, suma, 2);
    sumb += __shfl_xor_sync(0xffffffffu, sumb, 1);
    sumb += __shfl_xor_sync(0xffffffffu, sumb, 2);
    const float nla = g_nl[bh * S_ + rowa];
    const float nlb = g_nl[bh * S_ + rowb];
    const float inva = 1.f / (fmaxf(fabsf(suma), nla) + EPS_);
    const float invb = 1.f / (fmaxf(fabsf(sumb), nlb) + EPS_);

    float sa = 0.f, sb = 0.f;
    #pragma unroll
    for (int n = 0; n < 16; ++n) {
        sa += hacc[n][0] + hacc[n][1];
        sb += hacc[n][2] + hacc[n][3];
    }
    sa *= inva; sb *= invb;
    sa += __shfl_xor_sync(0xffffffffu, sa, 1);
    sa += __shfl_xor_sync(0xffffffffu, sa, 2);
    sb += __shfl_xor_sync(0xffffffffu, sb, 1);
    sb += __shfl_xor_sync(0xffffffffu, sb, 2);
    const float mua = sa * (1.f / 128.f), mub = sb * (1.f / 128.f);

    float va = 0.f, vbv = 0.f;
    #pragma unroll
    for (int n = 0; n < 16; ++n) {
        float d0 = hacc[n][0] * inva - mua, d1 = hacc[n][1] * inva - mua;
        float d2 = hacc[n][2] * invb - mub, d3 = hacc[n][3] * invb - mub;
        va += d0 * d0 + d1 * d1;
        vbv += d2 * d2 + d3 * d3;
    }
    va += __shfl_xor_sync(0xffffffffu, va, 1);
    va += __shfl_xor_sync(0xffffffffu, va, 2);
    vbv += __shfl_xor_sync(0xffffffffu, vbv, 1);
    vbv += __shfl_xor_sync(0xffffffffu, vbv, 2);
    const float rsa = rsqrtf(va * (1.f / 128.f) + EPS_);
    const float rsb = rsqrtf(vbv * (1.f / 128.f) + EPS_);

    float* outa = out + ((size_t)(b * S_ + rowa)) * E_ + h * DH_;
    float* outb = out + ((size_t)(b * S_ + rowb)) * E_ + h * DH_;
    #pragma unroll
    for (int n = 0; n < 16; ++n) {
        const int d = n * 8 + 2 * tig;
        const float l0 = lnsc[h * DH_ + d], l1 = lnsc[h * DH_ + d + 1];
        float2 oa, ob;
        oa.x = (hacc[n][0] * inva - mua) * rsa * l0;
        oa.y = (hacc[n][1] * inva - mua) * rsa * l1;
        ob.x = (hacc[n][2] * invb - mub) * rsb * l0;
        ob.y = (hacc[n][3] * invb - mub) * rsb * l1;
        *(float2*)(outa + d) = oa;
        *(float2*)(outb + d) = ob;
    }
}

// =====================================================================
extern "C" void kernel_launch(void* const* d_in, const int* in_sizes, int n_in,
                              void* d_out, int out_size)
{
    const float* q  = (const float*)d_in[0];
    const float* k  = (const float*)d_in[1];
    const float* v  = (const float*)d_in[2];
    const float* Wi = (const float*)d_in[3];
    const float* bi = (const float*)d_in[4];
    const float* Wf = (const float*)d_in[5];
    const float* bf = (const float*)d_in[6];
    const float* ln = (const float*)d_in[7];
    float* out = (float*)d_out;

    cudaFuncSetAttribute(attn_k, cudaFuncAttributeMaxDynamicSharedMemorySize, SM_BYTES);

    gates_partial_k<<<dim3(32, NEC), 256>>>(q, k, v, Wi, Wf);
    scan_k<<<B_ * NH_, 1024>>>(bi, bf);
    attn_k<<<dim3(B_ * NH_, 8), 256, SM_BYTES>>>(q, k, v, ln, out);
}

// round 16
// speedup vs baseline: 1.4961x; 1.0276x over previous
#include <cuda_runtime.h>
#include <cuda_fp16.h>
#include <math.h>
#include <stdint.h>

#define B_   2
#define S_   1024
#define E_   2048
#define NH_  16
#define DH_  128
#define EPS_ 1e-6f
#define NEC  24
#define ECH  256          // 6144 / 24, 4 sub-stages of 64

// ---------------- warp-MMA helpers (sm_80-era PTX: safe under compute_103) ----------------
static __device__ __forceinline__ uint32_t pack_hf2(float x0, float x1) {
    uint32_t r; asm("cvt.rn.f16x2.f32 %0, %1, %2;" : "=r"(r) : "f"(x1), "f"(x0)); return r;
}
static __device__ __forceinline__ uint32_t pack_bf2(float x0, float x1) {
    uint32_t r; asm("cvt.rn.bf16x2.f32 %0, %1, %2;" : "=r"(r) : "f"(x1), "f"(x0)); return r;
}
static __device__ __forceinline__ float lo_bf(uint32_t p) { return __uint_as_float(p << 16); }
static __device__ __forceinline__ float hi_bf(uint32_t p) { return __uint_as_float(p & 0xffff0000u); }

#define LDSM4(r, a) \
    asm volatile("ldmatrix.sync.aligned.m8n8.x4.shared.b16 {%0,%1,%2,%3}, [%4];" \
        : "=r"((r)[0]), "=r"((r)[1]), "=r"((r)[2]), "=r"((r)[3]) : "r"(a))
#define LDSM4T(r, a) \
    asm volatile("ldmatrix.sync.aligned.m8n8.x4.trans.shared.b16 {%0,%1,%2,%3}, [%4];" \
        : "=r"((r)[0]), "=r"((r)[1]), "=r"((r)[2]), "=r"((r)[3]) : "r"(a))

static __device__ __forceinline__ void mma16816h(float* c, const uint32_t* a, const uint32_t* b) {
    asm volatile("mma.sync.aligned.m16n8k16.row.col.f32.f16.f16.f32 "
        "{%0,%1,%2,%3}, {%4,%5,%6,%7}, {%8,%9}, {%0,%1,%2,%3};"
        : "+f"(c[0]), "+f"(c[1]), "+f"(c[2]), "+f"(c[3])
        : "r"(a[0]), "r"(a[1]), "r"(a[2]), "r"(a[3]), "r"(b[0]), "r"(b[1]));
}
static __device__ __forceinline__ void mma16816b(float* c, const uint32_t* a, const uint32_t* b) {
    asm volatile("mma.sync.aligned.m16n8k16.row.col.f32.bf16.bf16.f32 "
        "{%0,%1,%2,%3}, {%4,%5,%6,%7}, {%8,%9}, {%0,%1,%2,%3};"
        : "+f"(c[0]), "+f"(c[1]), "+f"(c[2]), "+f"(c[3])
        : "r"(a[0]), "r"(a[1]), "r"(a[2]), "r"(a[3]), "r"(b[0]), "r"(b[1]));
}

__device__ float g_part[2 * NEC * B_ * NH_ * S_];
__device__ float g_a [B_ * NH_ * S_];
__device__ float g_rm[B_ * NH_ * S_];
__device__ float g_nl[B_ * NH_ * S_];

// ============== Kernel 1: gates, bf16 3-term HMMA + register prefetch ==============
#define GLD 72

__global__ __launch_bounds__(256, 3) void gates_partial_k(
    const float* __restrict__ q, const float* __restrict__ k, const float* __restrict__ v,
    const float* __restrict__ Wi, const float* __restrict__ Wf)
{
    __shared__ __align__(16) unsigned short XsH[64 * GLD], XsL[64 * GLD];
    __shared__ __align__(16) unsigned short WsH[32 * GLD], WsL[32 * GLD];

    const int rt = blockIdx.x, ec = blockIdx.y;
    const int b = rt >> 4, s0 = (rt & 15) << 6, t = threadIdx.x;
    const int w = t >> 5, lane = t & 31;
    const int rw = w & 3;            // row-group (16 rows)
    const int kh = w >> 2;           // ee half: warps 0-3 -> 0, 4-7 -> 1
    const uint32_t xhB = (uint32_t)__cvta_generic_to_shared(XsH);
    const uint32_t xlB = (uint32_t)__cvta_generic_to_shared(XsL);
    const uint32_t whB = (uint32_t)__cvta_generic_to_shared(WsH);
    const uint32_t wlB = (uint32_t)__cvta_generic_to_shared(WsL);

    // fixed staging coordinates
    const int xr_ = t >> 4, xc4 = (t & 15) * 4;      // X: rows xr_, xr_+16.., col xc4
    const int wee = t >> 3, wcc = t & 7;             // W: ee wee (+32), col-group wcc

    float4 xreg[4], wreg[2];
    auto ldg_stage = [&](int sub) {
        const int e0 = ec * ECH + sub * 64;
        const float* xp = (e0 < E_) ? q : (e0 < 2 * E_) ? k : v;
        const int col0 = e0 & (E_ - 1);
        #pragma unroll
        for (int it = 0; it < 4; ++it)
            xreg[it] = *(const float4*)(xp + ((size_t)(b * S_ + s0 + xr_ + it * 16)) * E_ + col0 + xc4);
        #pragma unroll
        for (int it = 0; it < 2; ++it) {
            int eg = e0 + wee + it * 32;
            wreg[it] = (wcc < 4) ? *(const float4*)(Wi + eg * 16 + wcc * 4)
                                 : *(const float4*)(Wf + eg * 16 + (wcc - 4) * 4);
        }
    };

    float acc[4][4];
    #pragma unroll
    for (int j = 0; j < 4; ++j)
        #pragma unroll
        for (int e = 0; e < 4; ++e) acc[j][e] = 0.f;

    ldg_stage(0);

    #pragma unroll 1
    for (int sub = 0; sub < 4; ++sub) {
        __syncthreads();   // prev MMA reads done
        // ---- convert X regs -> bf16 hi/lo smem ----
        #pragma unroll
        for (int it = 0; it < 4; ++it) {
            float4 x = xreg[it];
            int r = xr_ + it * 16;
            uint32_t h01 = pack_bf2(x.x, x.y), h23 = pack_bf2(x.z, x.w);
            uint32_t l01 = pack_bf2(x.x - lo_bf(h01), x.y - hi_bf(h01));
            uint32_t l23 = pack_bf2(x.z - lo_bf(h23), x.w - hi_bf(h23));
            *(uint2*)((char*)XsH + (r * GLD + xc4) * 2) = make_uint2(h01, h23);
            *(uint2*)((char*)XsL + (r * GLD + xc4) * 2) = make_uint2(l01, l23);
        }
        // ---- convert W regs -> transposed [hcol][ee] bf16 hi/lo smem ----
        #pragma unroll
        for (int it = 0; it < 2; ++it) {
            float4 wv = wreg[it];
            int ee = wee + it * 32;
            const float wj[4] = {wv.x, wv.y, wv.z, wv.w};
            #pragma unroll
            for (int j = 0; j < 4; ++j) {
                int hcol = wcc * 4 + j;
                uint32_t p = pack_bf2(wj[j], 0.f);
                float hif = lo_bf(p);
                uint32_t pl = pack_bf2(wj[j] - hif, 0.f);
                WsH[hcol * GLD + ee] = (unsigned short)(p & 0xffffu);
                WsL[hcol * GLD + ee] = (unsigned short)(pl & 0xffffu);
            }
        }
        if (sub < 3) ldg_stage(sub + 1);   // latency drains behind barrier + MMA
        __syncthreads();
        // ---- MMA: warp = rows rw*16..+15, ee-half kh, 2 ksteps ----
        {
            const uint32_t rowa = (uint32_t)(rw * 16 + (lane & 15));
            const uint32_t asel = (uint32_t)((lane >> 4) * 8);
            const uint32_t rowk = (uint32_t)((lane & 7) + 8 * (lane >> 4));
            const uint32_t colk = (uint32_t)(8 * ((lane >> 3) & 1));
            #pragma unroll
            for (int ks = 0; ks < 2; ++ks) {
                const int kk = kh * 2 + ks;
                uint32_t aoff = (rowa * GLD + kk * 16 + asel) * 2;
                uint32_t ah[4], al[4];
                LDSM4(ah, xhB + aoff);
                LDSM4(al, xlB + aoff);
                uint32_t bh0[4], bh1[4], bl0[4], bl1[4];
                uint32_t boff0 = ((0 * 16 + rowk) * GLD + kk * 16 + colk) * 2;
                uint32_t boff1 = ((1 * 16 + rowk) * GLD + kk * 16 + colk) * 2;
                LDSM4(bh0, whB + boff0);
                LDSM4(bh1, whB + boff1);
                LDSM4(bl0, wlB + boff0);
                LDSM4(bl1, wlB + boff1);
                mma16816b(acc[0], ah, bh0);     mma16816b(acc[0], ah, bl0);     mma16816b(acc[0], al, bh0);
                mma16816b(acc[1], ah, bh0 + 2); mma16816b(acc[1], ah, bl0 + 2); mma16816b(acc[1], al, bh0 + 2);
                mma16816b(acc[2], ah, bh1);     mma16816b(acc[2], ah, bl1);     mma16816b(acc[2], al, bh1);
                mma16816b(acc[3], ah, bh1 + 2); mma16816b(acc[3], ah, bl1 + 2); mma16816b(acc[3], al, bh1 + 2);
            }
        }
    }

    // ---- cross-warp reduce (ee halves) + write g_part ----
    __syncthreads();
    float* red = (float*)XsH;
    if (kh == 1) {
        float* dst = red + ((w - 4) * 32 + lane) * 16;
        #pragma unroll
        for (int j = 0; j < 4; ++j)
            #pragma unroll
            for (int e = 0; e < 4; ++e) dst[j * 4 + e] = acc[j][e];
    }
    __syncthreads();
    if (kh == 0) {
        const float* src = red + (w * 32 + lane) * 16;
        #pragma unroll
        for (int j = 0; j < 4; ++j)
            #pragma unroll
            for (int e = 0; e < 4; ++e) acc[j][e] += src[j * 4 + e];
        const int r0 = s0 + rw * 16 + (lane >> 2);
        #pragma unroll
        for (int j = 0; j < 4; ++j) {
            #pragma unroll
            for (int e = 0; e < 4; ++e) {
                int s  = r0 + (e >> 1) * 8;
                int hcol = j * 8 + 2 * (lane & 3) + (e & 1);
                int gate = hcol >> 4, hm = hcol & 15;
                g_part[((gate * NEC + ec) * (B_ * NH_) + b * NH_ + hm) * S_ + s] = acc[j][e];
            }
        }
    }
}

// ============== Kernel 2: scans (unchanged) ==============
__global__ __launch_bounds__(1024, 1) void scan_k(const float* __restrict__ bi, const float* __restrict__ bf)
{
    __shared__ float buf[1024];
    const int bh = blockIdx.x, t = threadIdx.x, h = bh & 15;
    float ig = bi[h], fg = bf[h];
    #pragma unroll
    for (int ec = 0; ec < NEC; ++ec) {
        ig += g_part[((0 * NEC + ec) * (B_ * NH_) + bh) * S_ + t];
        fg += g_part[((1 * NEC + ec) * (B_ * NH_) + bh) * S_ + t];
    }
    float lf = fminf(fg, 0.f) - log1pf(expf(-fabsf(fg)));
    float x = lf;
    buf[t] = x; __syncthreads();
    for (int off = 1; off < 1024; off <<= 1) {
        float y = (t >= off) ? buf[t - off] : 0.f; __syncthreads();
        x += y; buf[t] = x; __syncthreads();
    }
    float cum = x, a = ig - cum;
    x = a; buf[t] = x; __syncthreads();
    for (int off = 1; off < 1024; off <<= 1) {
        float y = (t >= off) ? buf[t - off] : -3.4e38f; __syncthreads();
        x = fmaxf(x, y); buf[t] = x; __syncthreads();
    }
    g_a [bh * S_ + t] = a;
    g_rm[bh * S_ + t] = x;
    g_nl[bh * S_ + t] = expf(-(cum + x));
}

// ============== Kernel 3: HMMA plain-fp16 attention (R14, measured ~42us) ==============
#define LDH  136
#define SM_QHI 0
#define SM_KHI 34816
#define SM_VHI 52224
#define SM_AS  69632
#define SM_RMS 69888
#define SM_ERS 70400
#define SM_WCS 70912
#define SM_BYTES 71168

__global__ __launch_bounds__(256, 1) void attn_k(
    const float* __restrict__ q, const float* __restrict__ k,
    const float* __restrict__ v, const float* __restrict__ lnsc,
    float* __restrict__ out)
{
    extern __shared__ char smc[];
    const uint32_t smb = (uint32_t)__cvta_generic_to_shared(smc);
    float* aS  = (float*)(smc + SM_AS);
    float* rmS = (float*)(smc + SM_RMS);
    float* erS = (float*)(smc + SM_ERS);
    float* wcS = (float*)(smc + SM_WCS);

    const int bh = blockIdx.x;
    const int b  = bh >> 4, h = bh & 15;
    const int ri = 7 - (int)blockIdx.y;      // heavy CTAs first
    const int i0 = ri << 7;
    const int t  = threadIdx.x;
    const int w  = t >> 5, lane = t & 31;
    const int gid = lane >> 2, tig = lane & 3;
    const float scale = 0.08838834764831845f;

    // ---- Q load: fold scale, fp16 into padded row-major smem ----
    {
        const float* qb = q + ((size_t)(b * S_ + i0)) * E_ + h * DH_;
        #pragma unroll
        for (int it = 0; it < 16; ++it) {
            int idx = t + it * 256;
            int r = idx >> 5, d4 = (idx & 31) * 4;
            float4 x = *(const float4*)(qb + (size_t)r * E_ + d4);
            x.x *= scale; x.y *= scale; x.z *= scale; x.w *= scale;
            uint32_t h01 = pack_hf2(x.x, x.y), h23 = pack_hf2(x.z, x.w);
            uint32_t bo = (uint32_t)(r * LDH + d4) * 2;
            *(uint2*)(smc + SM_QHI + bo) = make_uint2(h01, h23);
        }
        if (t < 128) rmS[t] = g_rm[bh * S_ + i0 + t];
    }
    __syncthreads();

    // ---- cache Q fragments in registers (A-operand layout) ----
    uint32_t qh[8][4];
    {
        uint32_t rowq = (uint32_t)(w * 16 + (lane & 7) + 8 * ((lane >> 3) & 1));
        #pragma unroll
        for (int kk = 0; kk < 8; ++kk) {
            uint32_t off = (rowq * LDH + kk * 16 + 8 * (lane >> 4)) * 2;
            LDSM4(qh[kk], smb + SM_QHI + off);
        }
    }

    float hacc[16][4];
    #pragma unroll
    for (int n = 0; n < 16; ++n)
        #pragma unroll
        for (int e = 0; e < 4; ++e) hacc[n][e] = 0.f;
    float suma = 0.f, sumb = 0.f;

    const int rowa = i0 + w * 16 + gid;
    const int rowb = rowa + 8;
    const int nj = 2 * ri + 2;

    for (int jt = 0; jt < nj; ++jt) {
        const int j0 = jt << 6;
        __syncthreads();    // prev tile compute done before overwriting K/V/tables
        // ---- K,V tiles: fp16 ----
        {
            const float* kb = k + ((size_t)(b * S_ + j0)) * E_ + h * DH_;
            const float* vb = v + ((size_t)(b * S_ + j0)) * E_ + h * DH_;
            #pragma unroll
            for (int it = 0; it < 8; ++it) {
                int idx = t + it * 256;
                int r = idx >> 5, d4 = (idx & 31) * 4;
                uint32_t bo = (uint32_t)(r * LDH + d4) * 2;
                float4 x = *(const float4*)(kb + (size_t)r * E_ + d4);
                *(uint2*)(smc + SM_KHI + bo) = make_uint2(pack_hf2(x.x, x.y), pack_hf2(x.z, x.w));
                float4 y = *(const float4*)(vb + (size_t)r * E_ + d4);
                *(uint2*)(smc + SM_VHI + bo) = make_uint2(pack_hf2(y.x, y.y), pack_hf2(y.z, y.w));
            }
            if (t < 64) aS[t] = g_a[bh * S_ + j0 + t];
        }
        __syncthreads();
        // ---- exp tables ----
        if (t < 128) {
            float m0 = -3.4e38f;
            #pragma unroll 8
            for (int c = 0; c < 64; ++c) m0 = fmaxf(m0, aS[c]);
            if (t < 64) wcS[t] = __expf(aS[t] - m0);
            erS[t] = __expf(fminf(m0 - rmS[t], 80.f));
        }
        __syncthreads();

        // ---- QK: S = Q K^T ----
        float sacc[8][4];
        #pragma unroll
        for (int n = 0; n < 8; ++n)
            #pragma unroll
            for (int e = 0; e < 4; ++e) sacc[n][e] = 0.f;
        {
            uint32_t rowk = (uint32_t)((lane & 7) + 8 * (lane >> 4));
            uint32_t colk = (uint32_t)(8 * ((lane >> 3) & 1));
            #pragma unroll
            for (int kk = 0; kk < 8; ++kk) {
                #pragma unroll
                for (int np = 0; np < 4; ++np) {
                    uint32_t off = ((np * 16 + rowk) * LDH + kk * 16 + colk) * 2;
                    uint32_t bhf[4];
                    LDSM4(bhf, smb + SM_KHI + off);
                    mma16816h(sacc[2 * np],     qh[kk], bhf);
                    mma16816h(sacc[2 * np + 1], qh[kk], bhf + 2);
                }
            }
        }

        // ---- S -> P, causal mask, rowsums ----
        const float era = erS[w * 16 + gid];
        const float erb = erS[w * 16 + gid + 8];
        #pragma unroll
        for (int n = 0; n < 8; ++n) {
            const int cbase = n * 8 + 2 * tig;
            const int c0 = j0 + cbase, c1 = c0 + 1;
            const float w0 = wcS[cbase], w1 = wcS[cbase + 1];
            float p0 = (c0 <= rowa) ? sacc[n][0] * w0 * era : 0.f;
            float p1 = (c1 <= rowa) ? sacc[n][1] * w1 * era : 0.f;
            float p2 = (c0 <= rowb) ? sacc[n][2] * w0 * erb : 0.f;
            float p3 = (c1 <= rowb) ? sacc[n][3] * w1 * erb : 0.f;
            suma += p0 + p1; sumb += p2 + p3;
            sacc[n][0] = p0; sacc[n][1] = p1; sacc[n][2] = p2; sacc[n][3] = p3;
        }

        // ---- AV: H += P V ----
        {
            uint32_t rowv = (uint32_t)((lane & 7) + 8 * ((lane >> 3) & 1));
            uint32_t colv = (uint32_t)(8 * (lane >> 4));
            #pragma unroll
            for (int kk = 0; kk < 4; ++kk) {
                uint32_t pah[4];
                pah[0] = pack_hf2(sacc[2*kk][0],   sacc[2*kk][1]);
                pah[1] = pack_hf2(sacc[2*kk][2],   sacc[2*kk][3]);
                pah[2] = pack_hf2(sacc[2*kk+1][0], sacc[2*kk+1][1]);
                pah[3] = pack_hf2(sacc[2*kk+1][2], sacc[2*kk+1][3]);
                #pragma unroll
                for (int np = 0; np < 8; ++np) {
                    uint32_t off = ((kk * 16 + rowv) * LDH + np * 16 + colv) * 2;
                    uint32_t bvh[4];
                    LDSM4T(bvh, smb + SM_VHI + off);
                    mma16816h(hacc[2 * np],     pah, bvh);
                    mma16816h(hacc[2 * np + 1], pah, bvh + 2);
                }
            }
        }
    }

    // ---- epilogue ----
    suma += __shfl_xor_sync(0xffffffffu, suma, 1);
    suma += __shfl_xor_sync(0xffffffffu, suma, 2);
    sumb += __shfl_xor_sync(0xffffffffu, sumb, 1);
    sumb += __shfl_xor_sync(0xffffffffu, sumb, 2);
    const float nla = g_nl[bh * S_ + rowa];
    const float nlb = g_nl[bh * S_ + rowb];
    const float inva = 1.f / (fmaxf(fabsf(suma), nla) + EPS_);
    const float invb = 1.f / (fmaxf(fabsf(sumb), nlb) + EPS_);

    float sa = 0.f, sb = 0.f;
    #pragma unroll
    for (int n = 0; n < 16; ++n) {
        sa += hacc[n][0] + hacc[n][1];
        sb += hacc[n][2] + hacc[n][3];
    }
    sa *= inva; sb *= invb;
    sa += __shfl_xor_sync(0xffffffffu, sa, 1);
    sa += __shfl_xor_sync(0xffffffffu, sa, 2);
    sb += __shfl_xor_sync(0xffffffffu, sb, 1);
    sb += __shfl_xor_sync(0xffffffffu, sb, 2);
    const float mua = sa * (1.f / 128.f), mub = sb * (1.f / 128.f);

    float va = 0.f, vbv = 0.f;
    #pragma unroll
    for (int n = 0; n < 16; ++n) {
        float d0 = hacc[n][0] * inva - mua, d1 = hacc[n][1] * inva - mua;
        float d2 = hacc[n][2] * invb - mub, d3 = hacc[n][3] * invb - mub;
        va += d0 * d0 + d1 * d1;
        vbv += d2 * d2 + d3 * d3;
    }
    va += __shfl_xor_sync(0xffffffffu, va, 1);
    va += __shfl_xor_sync(0xffffffffu, va, 2);
    vbv += __shfl_xor_sync(0xffffffffu, vbv, 1);
    vbv += __shfl_xor_sync(0xffffffffu, vbv, 2);
    const float rsa = rsqrtf(va * (1.f / 128.f) + EPS_);
    const float rsb = rsqrtf(vbv * (1.f / 128.f) + EPS_);

    float* outa = out + ((size_t)(b * S_ + rowa)) * E_ + h * DH_;
    float* outb = out + ((size_t)(b * S_ + rowb)) * E_ + h * DH_;
    #pragma unroll
    for (int n = 0; n < 16; ++n) {
        const int d = n * 8 + 2 * tig;
        const float l0 = lnsc[h * DH_ + d], l1 = lnsc[h * DH_ + d + 1];
        float2 oa, ob;
        oa.x = (hacc[n][0] * inva - mua) * rsa * l0;
        oa.y = (hacc[n][1] * inva - mua) * rsa * l1;
        ob.x = (hacc[n][2] * invb - mub) * rsb * l0;
        ob.y = (hacc[n][3] * invb - mub) * rsb * l1;
        *(float2*)(outa + d) = oa;
        *(float2*)(outb + d) = ob;
    }
}

// =====================================================================
extern "C" void kernel_launch(void* const* d_in, const int* in_sizes, int n_in,
                              void* d_out, int out_size)
{
    const float* q  = (const float*)d_in[0];
    const float* k  = (const float*)d_in[1];
    const float* v  = (const float*)d_in[2];
    const float* Wi = (const float*)d_in[3];
    const float* bi = (const float*)d_in[4];
    const float* Wf = (const float*)d_in[5];
    const float* bf = (const float*)d_in[6];
    const float* ln = (const float*)d_in[7];
    float* out = (float*)d_out;

    cudaFuncSetAttribute(attn_k, cudaFuncAttributeMaxDynamicSharedMemorySize, SM_BYTES);

    gates_partial_k<<<dim3(32, NEC), 256>>>(q, k, v, Wi, Wf);
    scan_k<<<B_ * NH_, 1024>>>(bi, bf);
    attn_k<<<dim3(B_ * NH_, 8), 256, SM_BYTES>>>(q, k, v, ln, out);
}